// round 5
// baseline (speedup 1.0000x reference)
#include <cuda_runtime.h>
#include <cstdint>

#define HW 2
#define H 512
#define W 512
#define BX 32
#define BY 4
#define PPT 8                       // pixels per thread (vertical strip)
#define BLKY (BY * PPT)             // 32 rows covered per block
#define TILE_W (BX + 2*HW)          // 36
#define TILE_H (BLKY + 2*HW)        // 36

// scratch for the intermediate passes (allocation-free rule -> device globals)
__device__ float g_buf0[32 * H * W];
__device__ float g_buf1[32 * H * W];
__device__ int   g_need[3];         // per-pass: 1 = need full 5x5, 0 = 3x3 ok

__device__ __forceinline__ float ex2_approx(float x) {
    float y;
    asm("ex2.approx.ftz.f32 %0, %1;" : "=f"(y) : "f"(x));
    return y;
}

// ---------------- prologue: compute per-pass truncation flags ----------------
__global__ void compute_flags(const float* __restrict__ sigma_xyz,
                              const float* __restrict__ sigma_r)
{
    int p = threadIdx.x;
    if (p < 3) {
        float sx = sigma_xyz[2 * p + 0];
        float sy = sigma_xyz[2 * p + 1];
        float sr = sigma_r[p];
        float axn = 0.5f / (sx * sx);
        float ayn = 0.5f / (sy * sy);
        // error bound for dropping the 16 outer-ring taps:
        // per tap <= ws * sr * e^{-1/2}; den >= 1.
        float w1x = __expf(-axn), w4x = __expf(-4.f * axn);
        float w1y = __expf(-ayn), w4y = __expf(-4.f * ayn);
        float ring = 2.f * w4x * (1.f + 2.f * w1y + 2.f * w4y)
                   + 2.f * w4y * (1.f + 2.f * w1x);
        g_need[p] = (ring * 0.6065307f * sr < 1e-4f) ? 0 : 1;
    }
}

// ---------------- fast path: adaptive 3x3, rolling register window ----------------
__global__ __launch_bounds__(BX * BY) void bilateral_fast3x3(
    const float* __restrict__ in, float* __restrict__ out,
    const float* __restrict__ sigma_xyz, const float* __restrict__ sigma_r,
    int pass)
{
    if (g_need[pass]) return;        // uniform early exit; full kernel handles it

    __shared__ float tile[TILE_H][TILE_W];

    const int bx = blockIdx.x * BX;
    const int by = blockIdx.y * BLKY;
    const int b  = blockIdx.z;
    const float* img = in + (size_t)b * (H * W);

    const int t = threadIdx.y * BX + threadIdx.x;
    #pragma unroll
    for (int k = 0; k < (TILE_W * TILE_H + BX*BY - 1) / (BX*BY); k++) {
        int idx = t + k * (BX * BY);
        if (idx < TILE_W * TILE_H) {
            int ly = idx / TILE_W;
            int lx = idx - ly * TILE_W;
            int gx = min(max(bx + lx - HW, 0), W - 1);
            int gy = min(max(by + ly - HW, 0), H - 1);
            tile[ly][lx] = img[gy * W + gx];
        }
    }

    const float LOG2E = 1.4426950408889634f;
    const float sx = sigma_xyz[2 * pass + 0];
    const float sy = sigma_xyz[2 * pass + 1];
    const float sr = sigma_r[pass];
    const float axl = 0.5f / (sx * sx) * LOG2E;
    const float ayl = 0.5f / (sy * sy) * LOG2E;
    const float ar  = (0.5f / (sr * sr)) * LOG2E;
    const float nar = -ar;
    const float twoar = 2.0f * ar;
    const float axyl = axl + ayl;

    __syncthreads();

    const int tx = threadIdx.x;
    const int y0 = threadIdx.y * PPT;
    const int cx = tx + HW;

    float* orow = out + (size_t)b * (H * W) + (by + y0) * W + (bx + tx);

    float ra[3], rb[3], rc[3];
    #pragma unroll
    for (int j = 0; j < 3; j++) {
        ra[j] = tile[y0 + HW - 1][cx - 1 + j];
        rb[j] = tile[y0 + HW    ][cx - 1 + j];
    }

    #define TAP(NB, T0C) {                                   \
        const float nb = (NB);                               \
        const float u  = fmaf(nb, nar, t1);                  \
        const float w  = ex2_approx(fmaf(nb, u, (T0C)));     \
        num0 = fmaf(w, nb, num0);                            \
        den0 += w;                                           \
    }
    #define TAP2(NB, T0C) {                                  \
        const float nb = (NB);                               \
        const float u  = fmaf(nb, nar, t1);                  \
        const float w  = ex2_approx(fmaf(nb, u, (T0C)));     \
        num1 = fmaf(w, nb, num1);                            \
        den1 += w;                                           \
    }

    #pragma unroll
    for (int r = 0; r < PPT; r++) {
        const int py = y0 + HW + r;
        #pragma unroll
        for (int j = 0; j < 3; j++)
            rc[j] = tile[py + 1][cx - 1 + j];

        const float c  = rb[1];
        const float t1 = twoar * c;
        const float t0 = nar * c * c;
        const float t10 = t0 - axl;
        const float t01 = t0 - ayl;
        const float t11 = t0 - axyl;

        // center tap: arg == 0 -> w == 1 exactly
        float num0 = c,    den0 = 1.0f;
        float num1 = 0.f,  den1 = 0.0f;

        TAP (ra[0], t11)  TAP2(ra[1], t01)  TAP (ra[2], t11)
        TAP2(rb[0], t10)                    TAP (rb[2], t10)
        TAP2(rc[0], t11)  TAP (rc[1], t01)  TAP2(rc[2], t11)

        orow[r * W] = __fdividef(num0 + num1, den0 + den1);

        #pragma unroll
        for (int j = 0; j < 3; j++) { ra[j] = rb[j]; rb[j] = rc[j]; }
    }
    #undef TAP
    #undef TAP2
}

// ---------------- general path: full 5x5 from smem ----------------
__global__ __launch_bounds__(BX * BY) void bilateral_full5x5(
    const float* __restrict__ in, float* __restrict__ out,
    const float* __restrict__ sigma_xyz, const float* __restrict__ sigma_r,
    int pass)
{
    if (!g_need[pass]) return;       // uniform early exit; fast kernel handled it

    __shared__ float tile[TILE_H][TILE_W];

    const int bx = blockIdx.x * BX;
    const int by = blockIdx.y * BLKY;
    const int b  = blockIdx.z;
    const float* img = in + (size_t)b * (H * W);

    const int t = threadIdx.y * BX + threadIdx.x;
    #pragma unroll
    for (int k = 0; k < (TILE_W * TILE_H + BX*BY - 1) / (BX*BY); k++) {
        int idx = t + k * (BX * BY);
        if (idx < TILE_W * TILE_H) {
            int ly = idx / TILE_W;
            int lx = idx - ly * TILE_W;
            int gx = min(max(bx + lx - HW, 0), W - 1);
            int gy = min(max(by + ly - HW, 0), H - 1);
            tile[ly][lx] = img[gy * W + gx];
        }
    }

    const float LOG2E = 1.4426950408889634f;
    const float sx = sigma_xyz[2 * pass + 0];
    const float sy = sigma_xyz[2 * pass + 1];
    const float sr = sigma_r[pass];
    const float axl = 0.5f / (sx * sx) * LOG2E;
    const float ayl = 0.5f / (sy * sy) * LOG2E;
    const float ar  = (0.5f / (sr * sr)) * LOG2E;
    const float nar = -ar;
    const float twoar = 2.0f * ar;
    const float axyl = axl + ayl;
    const float a4x = 4.f * axl, a4y = 4.f * ayl;

    __syncthreads();

    const int tx = threadIdx.x;
    const int y0 = threadIdx.y * PPT;
    const int cx = tx + HW;

    float* orow = out + (size_t)b * (H * W) + (by + y0) * W + (bx + tx);

    #define TAP(NB, T0C) {                                   \
        const float nb = (NB);                               \
        const float u  = fmaf(nb, nar, t1);                  \
        const float w  = ex2_approx(fmaf(nb, u, (T0C)));     \
        num0 = fmaf(w, nb, num0);                            \
        den0 += w;                                           \
    }
    #define TAP2(NB, T0C) {                                  \
        const float nb = (NB);                               \
        const float u  = fmaf(nb, nar, t1);                  \
        const float w  = ex2_approx(fmaf(nb, u, (T0C)));     \
        num1 = fmaf(w, nb, num1);                            \
        den1 += w;                                           \
    }

    #pragma unroll
    for (int r = 0; r < PPT; r++) {
        const int py = y0 + HW + r;
        const float c  = tile[py][cx];
        const float t1 = twoar * c;
        const float t0 = nar * c * c;
        const float t10 = t0 - axl;
        const float t01 = t0 - ayl;
        const float t11 = t0 - axyl;
        const float t20 = t0 - a4x;
        const float t02 = t0 - a4y;
        const float t21 = t0 - (a4x + ayl);
        const float t12 = t0 - (axl + a4y);
        const float t22 = t0 - (a4x + a4y);

        float num0 = c,   den0 = 1.0f;
        float num1 = 0.f, den1 = 0.0f;

        #define DO_S(DY, DX, T0C)  TAP (tile[py + (DY)][cx + (DX)], T0C)
        #define DO_S2(DY, DX, T0C) TAP2(tile[py + (DY)][cx + (DX)], T0C)
        DO_S (-2,-2,t22) DO_S2(-2,-1,t12) DO_S (-2,0,t02) DO_S2(-2,1,t12) DO_S (-2,2,t22)
        DO_S2(-1,-2,t21) DO_S (-1,-1,t11) DO_S2(-1,0,t01) DO_S (-1,1,t11) DO_S2(-1,2,t21)
        DO_S ( 0,-2,t20) DO_S2( 0,-1,t10)                 DO_S2( 0,1,t10) DO_S ( 0,2,t20)
        DO_S2( 1,-2,t21) DO_S ( 1,-1,t11) DO_S2( 1,0,t01) DO_S ( 1,1,t11) DO_S2( 1,2,t21)
        DO_S ( 2,-2,t22) DO_S2( 2,-1,t12) DO_S ( 2,0,t02) DO_S2( 2,1,t12) DO_S ( 2,2,t22)
        #undef DO_S
        #undef DO_S2

        orow[r * W] = __fdividef(num0 + num1, den0 + den1);
    }
    #undef TAP
    #undef TAP2
}

extern "C" void kernel_launch(void* const* d_in, const int* in_sizes, int n_in,
                              void* d_out, int out_size)
{
    const float* x         = (const float*)d_in[0];
    const float* sigma_xyz = (const float*)d_in[1];
    const float* sigma_r   = (const float*)d_in[2];
    float* out = (float*)d_out;

    const int B = in_sizes[0] / (H * W);

    float* buf0;
    float* buf1;
    cudaGetSymbolAddress((void**)&buf0, g_buf0);
    cudaGetSymbolAddress((void**)&buf1, g_buf1);

    dim3 block(BX, BY, 1);
    dim3 grid(W / BX, H / BLKY, B);

    compute_flags<<<1, 32>>>(sigma_xyz, sigma_r);

    const float* src[3] = { x,    buf0, buf1 };
    float*       dst[3] = { buf0, buf1, out  };
    for (int p = 0; p < 3; p++) {
        bilateral_fast3x3<<<grid, block>>>(src[p], dst[p], sigma_xyz, sigma_r, p);
        bilateral_full5x5<<<grid, block>>>(src[p], dst[p], sigma_xyz, sigma_r, p);
    }
}

// round 6
// speedup vs baseline: 1.2278x; 1.2278x over previous
#include <cuda_runtime.h>
#include <cstdint>

#define HW 2
#define H 512
#define W 512

// ---- fast 3x3 kernel geometry: 2-wide x 4-tall per thread ----
#define FTX 16                       // threads x (each covers 2 pixels)
#define FTY 8                        // threads y
#define FPPT 4                       // pixel rows per thread
#define FBLKX 32                     // pixels covered in x
#define FBLKY (FTY * FPPT)           // 32 pixel rows per block
#define FT_W (FBLKX + 2)             // 34 (1-px halo)
#define FT_H (FBLKY + 2)             // 34

// ---- full 5x5 kernel geometry (unchanged) ----
#define BX 32
#define BY 4
#define PPT 8
#define BLKY (BY * PPT)
#define TILE_W (BX + 2*HW)           // 36
#define TILE_H (BLKY + 2*HW)         // 36

// scratch (allocation-free rule -> device globals)
__device__ float g_buf0[32 * H * W];
__device__ float g_buf1[32 * H * W];
__device__ int   g_need[3];          // per-pass: 1 = need full 5x5, 0 = 3x3 ok

__device__ __forceinline__ float ex2_approx(float x) {
    float y;
    asm("ex2.approx.ftz.f32 %0, %1;" : "=f"(y) : "f"(x));
    return y;
}

// ---------------- prologue: compute per-pass truncation flags ----------------
__global__ void compute_flags(const float* __restrict__ sigma_xyz,
                              const float* __restrict__ sigma_r)
{
    int p = threadIdx.x;
    if (p < 3) {
        float sx = sigma_xyz[2 * p + 0];
        float sy = sigma_xyz[2 * p + 1];
        float sr = sigma_r[p];
        float axn = 0.5f / (sx * sx);
        float ayn = 0.5f / (sy * sy);
        // error bound for dropping the 16 outer-ring taps:
        // per tap <= ws * sr * e^{-1/2}; den >= 1.
        float w1x = __expf(-axn), w4x = __expf(-4.f * axn);
        float w1y = __expf(-ayn), w4y = __expf(-4.f * ayn);
        float ring = 2.f * w4x * (1.f + 2.f * w1y + 2.f * w4y)
                   + 2.f * w4y * (1.f + 2.f * w1x);
        g_need[p] = (ring * 0.6065307f * sr < 1e-4f) ? 0 : 1;
    }
}

// ---------------- fast path: 3x3, 2-wide pixel packing ----------------
__global__ __launch_bounds__(FTX * FTY) void bilateral_fast3x3(
    const float* __restrict__ in, float* __restrict__ out,
    const float* __restrict__ sigma_xyz, const float* __restrict__ sigma_r,
    int pass)
{
    if (g_need[pass]) return;        // uniform early exit; full kernel handles it

    __shared__ float tile[FT_H][FT_W];

    const int bx = blockIdx.x * FBLKX;
    const int by = blockIdx.y * FBLKY;
    const int b  = blockIdx.z;
    const float* img = in + (size_t)b * (H * W);

    // cooperative tile load with replicate (clamp) padding, 1-px halo
    const int t = threadIdx.y * FTX + threadIdx.x;
    #pragma unroll
    for (int k = 0; k < (FT_W * FT_H + FTX*FTY - 1) / (FTX*FTY); k++) {
        int idx = t + k * (FTX * FTY);
        if (idx < FT_W * FT_H) {
            int ly = idx / FT_W;
            int lx = idx - ly * FT_W;
            int gx = min(max(bx + lx - 1, 0), W - 1);
            int gy = min(max(by + ly - 1, 0), H - 1);
            tile[ly][lx] = img[gy * W + gx];
        }
    }

    const float LOG2E = 1.4426950408889634f;
    const float sx = sigma_xyz[2 * pass + 0];
    const float sy = sigma_xyz[2 * pass + 1];
    const float sr = sigma_r[pass];
    const float axl = 0.5f / (sx * sx) * LOG2E;
    const float ayl = 0.5f / (sy * sy) * LOG2E;
    const float ar  = (0.5f / (sr * sr)) * LOG2E;
    const float nar = -ar;
    const float twoar = 2.0f * ar;
    const float axyl = axl + ayl;

    __syncthreads();

    const int tx = threadIdx.x;
    const int y0 = threadIdx.y * FPPT;           // first pixel row (local)
    const int c0 = 2 * tx;                       // window start col in tile

    float* orow = out + (size_t)b * (H * W) + (by + y0) * W + (bx + 2 * tx);

    #pragma unroll
    for (int r = 0; r < FPPT; r++) {
        const int tr = y0 + r;                   // top window row in tile
        // fresh vectorized window loads: 3 rows x 4 cols (8B-aligned)
        const float2 a01 = *(const float2*)&tile[tr    ][c0];
        const float2 a23 = *(const float2*)&tile[tr    ][c0 + 2];
        const float2 b01 = *(const float2*)&tile[tr + 1][c0];
        const float2 b23 = *(const float2*)&tile[tr + 1][c0 + 2];
        const float2 c01 = *(const float2*)&tile[tr + 2][c0];
        const float2 c23 = *(const float2*)&tile[tr + 2][c0 + 2];

        // ---- pixel 0: center = b01.y, window cols c0..c0+2 ----
        {
            const float c  = b01.y;
            const float t1 = twoar * c;
            const float t0 = nar * c * c;
            const float t10 = t0 - axl;
            const float t01v = t0 - ayl;
            const float t11 = t0 - axyl;
            float num0 = c,   den0 = 1.0f;
            float num1 = 0.f, den1 = 0.0f;
            #define TAPA(NB, T0C) {                                  \
                const float nb = (NB);                               \
                const float u  = fmaf(nb, nar, t1);                  \
                const float w  = ex2_approx(fmaf(nb, u, (T0C)));     \
                num0 = fmaf(w, nb, num0);  den0 += w; }
            #define TAPB(NB, T0C) {                                  \
                const float nb = (NB);                               \
                const float u  = fmaf(nb, nar, t1);                  \
                const float w  = ex2_approx(fmaf(nb, u, (T0C)));     \
                num1 = fmaf(w, nb, num1);  den1 += w; }
            TAPA(a01.x, t11) TAPB(a01.y, t01v) TAPA(a23.x, t11)
            TAPB(b01.x, t10)                   TAPA(b23.x, t10)
            TAPB(c01.x, t11) TAPA(c01.y, t01v) TAPB(c23.x, t11)
            const float r0 = __fdividef(num0 + num1, den0 + den1);

            // ---- pixel 1: center = b23.x, window cols c0+1..c0+3 ----
            const float c2  = b23.x;
            const float s1 = twoar * c2;
            const float s0 = nar * c2 * c2;
            const float s10 = s0 - axl;
            const float s01 = s0 - ayl;
            const float s11 = s0 - axyl;
            float num2 = c2,  den2 = 1.0f;
            float num3 = 0.f, den3 = 0.0f;
            #define TAPC(NB, T0C) {                                  \
                const float nb = (NB);                               \
                const float u  = fmaf(nb, nar, s1);                  \
                const float w  = ex2_approx(fmaf(nb, u, (T0C)));     \
                num2 = fmaf(w, nb, num2);  den2 += w; }
            #define TAPD(NB, T0C) {                                  \
                const float nb = (NB);                               \
                const float u  = fmaf(nb, nar, s1);                  \
                const float w  = ex2_approx(fmaf(nb, u, (T0C)));     \
                num3 = fmaf(w, nb, num3);  den3 += w; }
            TAPC(a01.y, s11) TAPD(a23.x, s01) TAPC(a23.y, s11)
            TAPD(b01.y, s10)                  TAPC(b23.y, s10)
            TAPD(c01.y, s11) TAPC(c23.x, s01) TAPD(c23.y, s11)
            const float r1 = __fdividef(num2 + num3, den2 + den3);

            *(float2*)&orow[r * W] = make_float2(r0, r1);
            #undef TAPA
            #undef TAPB
            #undef TAPC
            #undef TAPD
        }
    }
}

// ---------------- general path: full 5x5 from smem ----------------
__global__ __launch_bounds__(BX * BY) void bilateral_full5x5(
    const float* __restrict__ in, float* __restrict__ out,
    const float* __restrict__ sigma_xyz, const float* __restrict__ sigma_r,
    int pass)
{
    if (!g_need[pass]) return;       // uniform early exit; fast kernel handled it

    __shared__ float tile[TILE_H][TILE_W];

    const int bx = blockIdx.x * BX;
    const int by = blockIdx.y * BLKY;
    const int b  = blockIdx.z;
    const float* img = in + (size_t)b * (H * W);

    const int t = threadIdx.y * BX + threadIdx.x;
    #pragma unroll
    for (int k = 0; k < (TILE_W * TILE_H + BX*BY - 1) / (BX*BY); k++) {
        int idx = t + k * (BX * BY);
        if (idx < TILE_W * TILE_H) {
            int ly = idx / TILE_W;
            int lx = idx - ly * TILE_W;
            int gx = min(max(bx + lx - HW, 0), W - 1);
            int gy = min(max(by + ly - HW, 0), H - 1);
            tile[ly][lx] = img[gy * W + gx];
        }
    }

    const float LOG2E = 1.4426950408889634f;
    const float sx = sigma_xyz[2 * pass + 0];
    const float sy = sigma_xyz[2 * pass + 1];
    const float sr = sigma_r[pass];
    const float axl = 0.5f / (sx * sx) * LOG2E;
    const float ayl = 0.5f / (sy * sy) * LOG2E;
    const float ar  = (0.5f / (sr * sr)) * LOG2E;
    const float nar = -ar;
    const float twoar = 2.0f * ar;
    const float axyl = axl + ayl;
    const float a4x = 4.f * axl, a4y = 4.f * ayl;

    __syncthreads();

    const int tx = threadIdx.x;
    const int y0 = threadIdx.y * PPT;
    const int cx = tx + HW;

    float* orow = out + (size_t)b * (H * W) + (by + y0) * W + (bx + tx);

    #define TAP(NB, T0C) {                                   \
        const float nb = (NB);                               \
        const float u  = fmaf(nb, nar, t1);                  \
        const float w  = ex2_approx(fmaf(nb, u, (T0C)));     \
        num0 = fmaf(w, nb, num0);                            \
        den0 += w;                                           \
    }
    #define TAP2(NB, T0C) {                                  \
        const float nb = (NB);                               \
        const float u  = fmaf(nb, nar, t1);                  \
        const float w  = ex2_approx(fmaf(nb, u, (T0C)));     \
        num1 = fmaf(w, nb, num1);                            \
        den1 += w;                                           \
    }

    #pragma unroll
    for (int r = 0; r < PPT; r++) {
        const int py = y0 + HW + r;
        const float c  = tile[py][cx];
        const float t1 = twoar * c;
        const float t0 = nar * c * c;
        const float t10 = t0 - axl;
        const float t01 = t0 - ayl;
        const float t11 = t0 - axyl;
        const float t20 = t0 - a4x;
        const float t02 = t0 - a4y;
        const float t21 = t0 - (a4x + ayl);
        const float t12 = t0 - (axl + a4y);
        const float t22 = t0 - (a4x + a4y);

        float num0 = c,   den0 = 1.0f;
        float num1 = 0.f, den1 = 0.0f;

        #define DO_S(DY, DX, T0C)  TAP (tile[py + (DY)][cx + (DX)], T0C)
        #define DO_S2(DY, DX, T0C) TAP2(tile[py + (DY)][cx + (DX)], T0C)
        DO_S (-2,-2,t22) DO_S2(-2,-1,t12) DO_S (-2,0,t02) DO_S2(-2,1,t12) DO_S (-2,2,t22)
        DO_S2(-1,-2,t21) DO_S (-1,-1,t11) DO_S2(-1,0,t01) DO_S (-1,1,t11) DO_S2(-1,2,t21)
        DO_S ( 0,-2,t20) DO_S2( 0,-1,t10)                 DO_S2( 0,1,t10) DO_S ( 0,2,t20)
        DO_S2( 1,-2,t21) DO_S ( 1,-1,t11) DO_S2( 1,0,t01) DO_S ( 1,1,t11) DO_S2( 1,2,t21)
        DO_S ( 2,-2,t22) DO_S2( 2,-1,t12) DO_S ( 2,0,t02) DO_S2( 2,1,t12) DO_S ( 2,2,t22)
        #undef DO_S
        #undef DO_S2

        orow[r * W] = __fdividef(num0 + num1, den0 + den1);
    }
    #undef TAP
    #undef TAP2
}

extern "C" void kernel_launch(void* const* d_in, const int* in_sizes, int n_in,
                              void* d_out, int out_size)
{
    const float* x         = (const float*)d_in[0];
    const float* sigma_xyz = (const float*)d_in[1];
    const float* sigma_r   = (const float*)d_in[2];
    float* out = (float*)d_out;

    const int B = in_sizes[0] / (H * W);

    float* buf0;
    float* buf1;
    cudaGetSymbolAddress((void**)&buf0, g_buf0);
    cudaGetSymbolAddress((void**)&buf1, g_buf1);

    dim3 fblock(FTX, FTY, 1);
    dim3 fgrid(W / FBLKX, H / FBLKY, B);
    dim3 block(BX, BY, 1);
    dim3 grid(W / BX, H / BLKY, B);

    compute_flags<<<1, 32>>>(sigma_xyz, sigma_r);

    const float* src[3] = { x,    buf0, buf1 };
    float*       dst[3] = { buf0, buf1, out  };
    for (int p = 0; p < 3; p++) {
        bilateral_fast3x3<<<fgrid, fblock>>>(src[p], dst[p], sigma_xyz, sigma_r, p);
        bilateral_full5x5<<<grid, block>>>(src[p], dst[p], sigma_xyz, sigma_r, p);
    }
}

// round 7
// speedup vs baseline: 1.4787x; 1.2043x over previous
#include <cuda_runtime.h>
#include <cstdint>

#define HW 2
#define H 512
#define W 512

// ---- fast 3x3 kernel geometry: 4-wide x 4-tall per thread, direct gmem ----
#define GTX 8                        // threads x (each covers 4 px)
#define GTY 16                       // threads y (each covers 4 rows)
#define GBLKX 32                     // px per block in x
#define GBLKY 64                     // px per block in y

// ---- full 5x5 kernel geometry (fallback, smem) ----
#define BX 32
#define BY 4
#define PPT 8
#define BLKY (BY * PPT)
#define TILE_W (BX + 2*HW)           // 36
#define TILE_H (BLKY + 2*HW)         // 36

// scratch (allocation-free rule -> device globals)
__device__ float g_buf0[32 * H * W];
__device__ float g_buf1[32 * H * W];

__device__ __forceinline__ float ex2_approx(float x) {
    float y;
    asm("ex2.approx.ftz.f32 %0, %1;" : "=f"(y) : "f"(x));
    return y;
}

// outer-ring truncation decision: error bound for dropping the 16 |d|=2 taps,
// per tap <= ws * sr * e^{-1/2}; den >= 1. Uniform across the launch.
__device__ __forceinline__ bool need_outer_ring(float sx, float sy, float sr) {
    float axn = 0.5f / (sx * sx);
    float ayn = 0.5f / (sy * sy);
    float w1x = __expf(-axn), w4x = __expf(-4.f * axn);
    float w1y = __expf(-ayn), w4y = __expf(-4.f * ayn);
    float ring = 2.f * w4x * (1.f + 2.f * w1y + 2.f * w4y)
               + 2.f * w4y * (1.f + 2.f * w1x);
    return !(ring * 0.6065307f * sr < 1e-4f);
}

// ---------------- fast path: adaptive 3x3, direct gmem, register row ring ----------------
__global__ __launch_bounds__(GTX * GTY) void bilateral_fast3x3(
    const float* __restrict__ in, float* __restrict__ out,
    const float* __restrict__ sigma_xyz, const float* __restrict__ sigma_r,
    int pass)
{
    const float LOG2E = 1.4426950408889634f;
    const float sx = sigma_xyz[2 * pass + 0];
    const float sy = sigma_xyz[2 * pass + 1];
    const float sr = sigma_r[pass];
    if (need_outer_ring(sx, sy, sr)) return;   // uniform: full5x5 kernel handles it

    const float axl = 0.5f / (sx * sx) * LOG2E;
    const float ayl = 0.5f / (sy * sy) * LOG2E;
    const float ar  = (0.5f / (sr * sr)) * LOG2E;
    const float nar = -ar;
    const float twoar = 2.0f * ar;
    const float axyl = axl + ayl;

    const int b   = blockIdx.z;
    const int gx0 = blockIdx.x * GBLKX + threadIdx.x * 4;   // first pixel col
    const int gy0 = blockIdx.y * GBLKY + threadIdx.y * 4;   // first pixel row
    const float* img = in  + (size_t)b * (H * W);
    float*       op  = out + (size_t)b * (H * W);

    // clamped edge columns (only ones that can go OOB)
    const int xm1 = max(gx0 - 1, 0);
    const int xp4 = min(gx0 + 4, W - 1);

    // 4-slot row ring, 6 floats per row (cols gx0-1 .. gx0+4)
    float rows[4][6];

    #define LOAD_ROW(SLOT, RY) {                                        \
        const int ryc = min(max((RY), 0), H - 1);                       \
        const float* rp = img + ryc * W;                                \
        const float4 m = *(const float4*)(rp + gx0);                    \
        rows[SLOT][0] = rp[xm1];                                        \
        rows[SLOT][1] = m.x; rows[SLOT][2] = m.y;                       \
        rows[SLOT][3] = m.z; rows[SLOT][4] = m.w;                       \
        rows[SLOT][5] = rp[xp4];                                        \
    }

    // prime: rows gy0-1, gy0, gy0+1
    LOAD_ROW(0, gy0 - 1)
    LOAD_ROW(1, gy0)
    LOAD_ROW(2, gy0 + 1)

    #pragma unroll
    for (int r = 0; r < 4; r++) {
        // prefetch next bottom row (one iteration ahead)
        if (r < 3) LOAD_ROW((r + 3) & 3, gy0 + 2 + r)

        const float* top = rows[(r    ) & 3];
        const float* mid = rows[(r + 1) & 3];
        const float* bot = rows[(r + 2) & 3];

        float4 res;
        float* resp = &res.x;
        #pragma unroll
        for (int i = 0; i < 4; i++) {
            const float c  = mid[i + 1];
            const float t1 = twoar * c;
            const float t0 = nar * c * c;
            const float t10 = t0 - axl;
            const float t01 = t0 - ayl;
            const float t11 = t0 - axyl;

            // center tap: arg == 0 -> w == 1 exactly
            float num0 = c,   den0 = 1.0f;
            float num1 = 0.f, den1 = 0.0f;

            #define TAPA(NB, T0C) {                                  \
                const float nb = (NB);                               \
                const float u  = fmaf(nb, nar, t1);                  \
                const float w  = ex2_approx(fmaf(nb, u, (T0C)));     \
                num0 = fmaf(w, nb, num0);  den0 += w; }
            #define TAPB(NB, T0C) {                                  \
                const float nb = (NB);                               \
                const float u  = fmaf(nb, nar, t1);                  \
                const float w  = ex2_approx(fmaf(nb, u, (T0C)));     \
                num1 = fmaf(w, nb, num1);  den1 += w; }

            TAPA(top[i], t11) TAPB(top[i+1], t01) TAPA(top[i+2], t11)
            TAPB(mid[i], t10)                     TAPA(mid[i+2], t10)
            TAPB(bot[i], t11) TAPA(bot[i+1], t01) TAPB(bot[i+2], t11)
            #undef TAPA
            #undef TAPB

            resp[i] = __fdividef(num0 + num1, den0 + den1);
        }

        *(float4*)(op + (gy0 + r) * W + gx0) = res;
    }
    #undef LOAD_ROW
}

// ---------------- general path: full 5x5 from smem ----------------
__global__ __launch_bounds__(BX * BY) void bilateral_full5x5(
    const float* __restrict__ in, float* __restrict__ out,
    const float* __restrict__ sigma_xyz, const float* __restrict__ sigma_r,
    int pass)
{
    const float LOG2E = 1.4426950408889634f;
    const float sx = sigma_xyz[2 * pass + 0];
    const float sy = sigma_xyz[2 * pass + 1];
    const float sr = sigma_r[pass];
    if (!need_outer_ring(sx, sy, sr)) return;  // uniform: fast kernel handled it

    __shared__ float tile[TILE_H][TILE_W];

    const int bx = blockIdx.x * BX;
    const int by = blockIdx.y * BLKY;
    const int b  = blockIdx.z;
    const float* img = in + (size_t)b * (H * W);

    const int t = threadIdx.y * BX + threadIdx.x;
    #pragma unroll
    for (int k = 0; k < (TILE_W * TILE_H + BX*BY - 1) / (BX*BY); k++) {
        int idx = t + k * (BX * BY);
        if (idx < TILE_W * TILE_H) {
            int ly = idx / TILE_W;
            int lx = idx - ly * TILE_W;
            int gx = min(max(bx + lx - HW, 0), W - 1);
            int gy = min(max(by + ly - HW, 0), H - 1);
            tile[ly][lx] = img[gy * W + gx];
        }
    }

    const float axl = 0.5f / (sx * sx) * LOG2E;
    const float ayl = 0.5f / (sy * sy) * LOG2E;
    const float ar  = (0.5f / (sr * sr)) * LOG2E;
    const float nar = -ar;
    const float twoar = 2.0f * ar;
    const float axyl = axl + ayl;
    const float a4x = 4.f * axl, a4y = 4.f * ayl;

    __syncthreads();

    const int tx = threadIdx.x;
    const int y0 = threadIdx.y * PPT;
    const int cx = tx + HW;

    float* orow = out + (size_t)b * (H * W) + (by + y0) * W + (bx + tx);

    #define TAP(NB, T0C) {                                   \
        const float nb = (NB);                               \
        const float u  = fmaf(nb, nar, t1);                  \
        const float w  = ex2_approx(fmaf(nb, u, (T0C)));     \
        num0 = fmaf(w, nb, num0);                            \
        den0 += w;                                           \
    }
    #define TAP2(NB, T0C) {                                  \
        const float nb = (NB);                               \
        const float u  = fmaf(nb, nar, t1);                  \
        const float w  = ex2_approx(fmaf(nb, u, (T0C)));     \
        num1 = fmaf(w, nb, num1);                            \
        den1 += w;                                           \
    }

    #pragma unroll
    for (int r = 0; r < PPT; r++) {
        const int py = y0 + HW + r;
        const float c  = tile[py][cx];
        const float t1 = twoar * c;
        const float t0 = nar * c * c;
        const float t10 = t0 - axl;
        const float t01 = t0 - ayl;
        const float t11 = t0 - axyl;
        const float t20 = t0 - a4x;
        const float t02 = t0 - a4y;
        const float t21 = t0 - (a4x + ayl);
        const float t12 = t0 - (axl + a4y);
        const float t22 = t0 - (a4x + a4y);

        float num0 = c,   den0 = 1.0f;
        float num1 = 0.f, den1 = 0.0f;

        #define DO_S(DY, DX, T0C)  TAP (tile[py + (DY)][cx + (DX)], T0C)
        #define DO_S2(DY, DX, T0C) TAP2(tile[py + (DY)][cx + (DX)], T0C)
        DO_S (-2,-2,t22) DO_S2(-2,-1,t12) DO_S (-2,0,t02) DO_S2(-2,1,t12) DO_S (-2,2,t22)
        DO_S2(-1,-2,t21) DO_S (-1,-1,t11) DO_S2(-1,0,t01) DO_S (-1,1,t11) DO_S2(-1,2,t21)
        DO_S ( 0,-2,t20) DO_S2( 0,-1,t10)                 DO_S2( 0,1,t10) DO_S ( 0,2,t20)
        DO_S2( 1,-2,t21) DO_S ( 1,-1,t11) DO_S2( 1,0,t01) DO_S ( 1,1,t11) DO_S2( 1,2,t21)
        DO_S ( 2,-2,t22) DO_S2( 2,-1,t12) DO_S ( 2,0,t02) DO_S2( 2,1,t12) DO_S ( 2,2,t22)
        #undef DO_S
        #undef DO_S2

        orow[r * W] = __fdividef(num0 + num1, den0 + den1);
    }
    #undef TAP
    #undef TAP2
}

extern "C" void kernel_launch(void* const* d_in, const int* in_sizes, int n_in,
                              void* d_out, int out_size)
{
    const float* x         = (const float*)d_in[0];
    const float* sigma_xyz = (const float*)d_in[1];
    const float* sigma_r   = (const float*)d_in[2];
    float* out = (float*)d_out;

    const int B = in_sizes[0] / (H * W);

    float* buf0;
    float* buf1;
    cudaGetSymbolAddress((void**)&buf0, g_buf0);
    cudaGetSymbolAddress((void**)&buf1, g_buf1);

    dim3 fblock(GTX, GTY, 1);
    dim3 fgrid(W / GBLKX, H / GBLKY, B);
    dim3 block(BX, BY, 1);
    dim3 grid(W / BX, H / BLKY, B);

    const float* src[3] = { x,    buf0, buf1 };
    float*       dst[3] = { buf0, buf1, out  };
    for (int p = 0; p < 3; p++) {
        bilateral_fast3x3<<<fgrid, fblock>>>(src[p], dst[p], sigma_xyz, sigma_r, p);
        bilateral_full5x5<<<grid, block>>>(src[p], dst[p], sigma_xyz, sigma_r, p);
    }
}

// round 8
// speedup vs baseline: 1.6400x; 1.1091x over previous
#include <cuda_runtime.h>
#include <cstdint>

#define HW 2
#define H 512
#define W 512

// ---- fast 3x3 kernel geometry: 4-wide x 4-tall per thread, direct gmem ----
#define GTX 8                        // threads x (each covers 4 px)
#define GTY 16                       // threads y (each covers 4 rows)
#define GBLKX 32                     // px per block in x
#define GBLKY 64                     // px per block in y

// ---- full 5x5 kernel geometry (fallback, smem, persistent) ----
#define BX 32
#define BY 4
#define PPT 8
#define BLKY (BY * PPT)
#define TILE_W (BX + 2*HW)           // 36
#define TILE_H (BLKY + 2*HW)         // 36
#define FB_GRID 296                  // persistent fallback grid (2*148)

// scratch (allocation-free rule -> device globals)
__device__ float g_buf0[32 * H * W];
__device__ float g_buf1[32 * H * W];

__device__ __forceinline__ float ex2_approx(float x) {
    float y;
    asm("ex2.approx.ftz.f32 %0, %1;" : "=f"(y) : "f"(x));
    return y;
}

// packed f32x2 helpers (Blackwell FFMA2/FADD2 — only reachable via PTX)
__device__ __forceinline__ unsigned long long pack2(float lo, float hi) {
    unsigned long long r;
    asm("mov.b64 %0, {%1, %2};" : "=l"(r) : "f"(lo), "f"(hi));
    return r;
}
__device__ __forceinline__ void unpack2(unsigned long long v, float& lo, float& hi) {
    asm("mov.b64 {%0, %1}, %2;" : "=f"(lo), "=f"(hi) : "l"(v));
}
__device__ __forceinline__ unsigned long long fma2(unsigned long long a,
                                                   unsigned long long b,
                                                   unsigned long long c) {
    unsigned long long r;
    asm("fma.rn.f32x2 %0, %1, %2, %3;" : "=l"(r) : "l"(a), "l"(b), "l"(c));
    return r;
}
__device__ __forceinline__ unsigned long long add2(unsigned long long a,
                                                   unsigned long long b) {
    unsigned long long r;
    asm("add.rn.f32x2 %0, %1, %2;" : "=l"(r) : "l"(a), "l"(b));
    return r;
}

// outer-ring truncation decision: error bound for dropping the 16 |d|=2 taps,
// per tap <= ws * sr * e^{-1/2}; den >= 1. Uniform across the launch.
__device__ __forceinline__ bool need_outer_ring(float sx, float sy, float sr) {
    float axn = 0.5f / (sx * sx);
    float ayn = 0.5f / (sy * sy);
    float w1x = __expf(-axn), w4x = __expf(-4.f * axn);
    float w1y = __expf(-ayn), w4y = __expf(-4.f * ayn);
    float ring = 2.f * w4x * (1.f + 2.f * w1y + 2.f * w4y)
               + 2.f * w4y * (1.f + 2.f * w1x);
    return !(ring * 0.6065307f * sr < 1e-4f);
}

// ---------------- fast path: adaptive 3x3, direct gmem, f32x2 packed taps ----------------
__global__ __launch_bounds__(GTX * GTY) void bilateral_fast3x3(
    const float* __restrict__ in, float* __restrict__ out,
    const float* __restrict__ sigma_xyz, const float* __restrict__ sigma_r,
    int pass)
{
    const float LOG2E = 1.4426950408889634f;
    const float sx = sigma_xyz[2 * pass + 0];
    const float sy = sigma_xyz[2 * pass + 1];
    const float sr = sigma_r[pass];
    if (need_outer_ring(sx, sy, sr)) return;   // uniform: full5x5 kernel handles it

    const float axl = 0.5f / (sx * sx) * LOG2E;
    const float ayl = 0.5f / (sy * sy) * LOG2E;
    const float ar  = (0.5f / (sr * sr)) * LOG2E;
    const float nar = -ar;
    const float twoar = 2.0f * ar;
    const float axyl = axl + ayl;

    const unsigned long long nar2 = pack2(nar, nar);

    const int b   = blockIdx.z;
    const int gx0 = blockIdx.x * GBLKX + threadIdx.x * 4;   // first pixel col
    const int gy0 = blockIdx.y * GBLKY + threadIdx.y * 4;   // first pixel row
    const float* img = in  + (size_t)b * (H * W);
    float*       op  = out + (size_t)b * (H * W);

    // clamped edge columns (only ones that can go OOB)
    const int xm1 = max(gx0 - 1, 0);
    const int xp4 = min(gx0 + 4, W - 1);

    // 4-slot row ring, 6 floats per row (cols gx0-1 .. gx0+4)
    float rows[4][6];

    #define LOAD_ROW(SLOT, RY) {                                        \
        const int ryc = min(max((RY), 0), H - 1);                       \
        const float* rp = img + ryc * W;                                \
        const float4 m = *(const float4*)(rp + gx0);                    \
        rows[SLOT][0] = rp[xm1];                                        \
        rows[SLOT][1] = m.x; rows[SLOT][2] = m.y;                       \
        rows[SLOT][3] = m.z; rows[SLOT][4] = m.w;                       \
        rows[SLOT][5] = rp[xp4];                                        \
    }

    // prime: rows gy0-1, gy0, gy0+1
    LOAD_ROW(0, gy0 - 1)
    LOAD_ROW(1, gy0)
    LOAD_ROW(2, gy0 + 1)

    #pragma unroll
    for (int r = 0; r < 4; r++) {
        // prefetch next bottom row (one iteration ahead)
        if (r < 3) LOAD_ROW((r + 3) & 3, gy0 + 2 + r)

        const float* top = rows[(r    ) & 3];
        const float* mid = rows[(r + 1) & 3];
        const float* bot = rows[(r + 2) & 3];

        float4 res;
        float* resp = &res.x;
        #pragma unroll
        for (int i = 0; i < 4; i++) {
            const float c  = mid[i + 1];
            const float t1 = twoar * c;
            const float t0 = nar * c * c;
            const float t10 = t0 - axl;
            const float t01 = t0 - ayl;
            const float t11 = t0 - axyl;

            const unsigned long long t1_2 = pack2(t1, t1);

            // packed accumulators; center tap (w==1) folded into init
            unsigned long long num2 = pack2(c, 0.f);
            unsigned long long den2 = pack2(1.f, 0.f);

            // paired taps: all f32x2 math except the two scalar EX2s
            #define TAPP(NB_A, T0A, NB_B, T0B) {                          \
                const unsigned long long nb2 = pack2((NB_A), (NB_B));     \
                const unsigned long long u2  = fma2(nb2, nar2, t1_2);     \
                const unsigned long long g2  = fma2(nb2, u2,              \
                                                    pack2((T0A), (T0B))); \
                float ga, gb;  unpack2(g2, ga, gb);                       \
                const unsigned long long w2 = pack2(ex2_approx(ga),       \
                                                    ex2_approx(gb));      \
                num2 = fma2(w2, nb2, num2);                               \
                den2 = add2(den2, w2);                                    \
            }

            TAPP(top[i],   t11, top[i+1], t01)
            TAPP(top[i+2], t11, mid[i],   t10)
            TAPP(mid[i+2], t10, bot[i],   t11)
            TAPP(bot[i+1], t01, bot[i+2], t11)
            #undef TAPP

            float na, nb_, da, db;
            unpack2(num2, na, nb_);
            unpack2(den2, da, db);
            resp[i] = __fdividef(na + nb_, da + db);
        }

        *(float4*)(op + (gy0 + r) * W + gx0) = res;
    }
    #undef LOAD_ROW
}

// ---------------- general path: full 5x5 from smem, persistent grid-stride ----------------
__global__ __launch_bounds__(BX * BY) void bilateral_full5x5(
    const float* __restrict__ in, float* __restrict__ out,
    const float* __restrict__ sigma_xyz, const float* __restrict__ sigma_r,
    int pass, int batch)
{
    const float LOG2E = 1.4426950408889634f;
    const float sx = sigma_xyz[2 * pass + 0];
    const float sy = sigma_xyz[2 * pass + 1];
    const float sr = sigma_r[pass];
    if (!need_outer_ring(sx, sy, sr)) return;  // uniform: fast kernel handled it

    __shared__ float tile[TILE_H][TILE_W];

    const float axl = 0.5f / (sx * sx) * LOG2E;
    const float ayl = 0.5f / (sy * sy) * LOG2E;
    const float ar  = (0.5f / (sr * sr)) * LOG2E;
    const float nar = -ar;
    const float twoar = 2.0f * ar;
    const float axyl = axl + ayl;
    const float a4x = 4.f * axl, a4y = 4.f * ayl;

    const int tiles_x = W / BX;
    const int tiles_y = H / BLKY;
    const int tile_total = tiles_x * tiles_y * batch;
    const int t = threadIdx.y * BX + threadIdx.x;
    const int tx = threadIdx.x;
    const int y0 = threadIdx.y * PPT;
    const int cx = tx + HW;

    for (int tid = blockIdx.x; tid < tile_total; tid += gridDim.x) {
        const int b   = tid / (tiles_x * tiles_y);
        const int rem = tid - b * (tiles_x * tiles_y);
        const int bx = (rem % tiles_x) * BX;
        const int by = (rem / tiles_x) * BLKY;
        const float* img = in + (size_t)b * (H * W);

        __syncthreads();   // protect smem reuse across tile iterations
        #pragma unroll
        for (int k = 0; k < (TILE_W * TILE_H + BX*BY - 1) / (BX*BY); k++) {
            int idx = t + k * (BX * BY);
            if (idx < TILE_W * TILE_H) {
                int ly = idx / TILE_W;
                int lx = idx - ly * TILE_W;
                int gx = min(max(bx + lx - HW, 0), W - 1);
                int gy = min(max(by + ly - HW, 0), H - 1);
                tile[ly][lx] = img[gy * W + gx];
            }
        }
        __syncthreads();

        float* orow = out + (size_t)b * (H * W) + (by + y0) * W + (bx + tx);

        #define TAP(NB, T0C) {                                   \
            const float nb = (NB);                               \
            const float u  = fmaf(nb, nar, t1);                  \
            const float w  = ex2_approx(fmaf(nb, u, (T0C)));     \
            num0 = fmaf(w, nb, num0);                            \
            den0 += w;                                           \
        }
        #define TAP2(NB, T0C) {                                  \
            const float nb = (NB);                               \
            const float u  = fmaf(nb, nar, t1);                  \
            const float w  = ex2_approx(fmaf(nb, u, (T0C)));     \
            num1 = fmaf(w, nb, num1);                            \
            den1 += w;                                           \
        }

        #pragma unroll
        for (int r = 0; r < PPT; r++) {
            const int py = y0 + HW + r;
            const float c  = tile[py][cx];
            const float t1 = twoar * c;
            const float t0 = nar * c * c;
            const float t10 = t0 - axl;
            const float t01 = t0 - ayl;
            const float t11 = t0 - axyl;
            const float t20 = t0 - a4x;
            const float t02 = t0 - a4y;
            const float t21 = t0 - (a4x + ayl);
            const float t12 = t0 - (axl + a4y);
            const float t22 = t0 - (a4x + a4y);

            float num0 = c,   den0 = 1.0f;
            float num1 = 0.f, den1 = 0.0f;

            #define DO_S(DY, DX, T0C)  TAP (tile[py + (DY)][cx + (DX)], T0C)
            #define DO_S2(DY, DX, T0C) TAP2(tile[py + (DY)][cx + (DX)], T0C)
            DO_S (-2,-2,t22) DO_S2(-2,-1,t12) DO_S (-2,0,t02) DO_S2(-2,1,t12) DO_S (-2,2,t22)
            DO_S2(-1,-2,t21) DO_S (-1,-1,t11) DO_S2(-1,0,t01) DO_S (-1,1,t11) DO_S2(-1,2,t21)
            DO_S ( 0,-2,t20) DO_S2( 0,-1,t10)                 DO_S2( 0,1,t10) DO_S ( 0,2,t20)
            DO_S2( 1,-2,t21) DO_S ( 1,-1,t11) DO_S2( 1,0,t01) DO_S ( 1,1,t11) DO_S2( 1,2,t21)
            DO_S ( 2,-2,t22) DO_S2( 2,-1,t12) DO_S ( 2,0,t02) DO_S2( 2,1,t12) DO_S ( 2,2,t22)
            #undef DO_S
            #undef DO_S2

            orow[r * W] = __fdividef(num0 + num1, den0 + den1);
        }
        #undef TAP
        #undef TAP2
    }
}

extern "C" void kernel_launch(void* const* d_in, const int* in_sizes, int n_in,
                              void* d_out, int out_size)
{
    const float* x         = (const float*)d_in[0];
    const float* sigma_xyz = (const float*)d_in[1];
    const float* sigma_r   = (const float*)d_in[2];
    float* out = (float*)d_out;

    const int B = in_sizes[0] / (H * W);

    float* buf0;
    float* buf1;
    cudaGetSymbolAddress((void**)&buf0, g_buf0);
    cudaGetSymbolAddress((void**)&buf1, g_buf1);

    dim3 fblock(GTX, GTY, 1);
    dim3 fgrid(W / GBLKX, H / GBLKY, B);
    dim3 block(BX, BY, 1);

    const float* src[3] = { x,    buf0, buf1 };
    float*       dst[3] = { buf0, buf1, out  };
    for (int p = 0; p < 3; p++) {
        bilateral_fast3x3<<<fgrid, fblock>>>(src[p], dst[p], sigma_xyz, sigma_r, p);
        bilateral_full5x5<<<FB_GRID, block>>>(src[p], dst[p], sigma_xyz, sigma_r, p, B);
    }
}

// round 9
// speedup vs baseline: 1.9189x; 1.1700x over previous
#include <cuda_runtime.h>
#include <cstdint>

#define HW 2
#define H 512
#define W 512

// ---- geometry: 4-wide x 4-tall per thread, direct gmem ----
#define GTX 8                        // threads x (each covers 4 px)
#define GTY 16                       // threads y (each covers 4 rows)
#define GBLKX 32                     // px per block in x
#define GBLKY 64                     // px per block in y

// scratch (allocation-free rule -> device globals)
__device__ float g_buf0[32 * H * W];
__device__ float g_buf1[32 * H * W];

__device__ __forceinline__ float ex2_approx(float x) {
    float y;
    asm("ex2.approx.ftz.f32 %0, %1;" : "=f"(y) : "f"(x));
    return y;
}

// packed f32x2 helpers (Blackwell FFMA2/FADD2/FMUL2 — only reachable via PTX)
__device__ __forceinline__ unsigned long long pack2(float lo, float hi) {
    unsigned long long r;
    asm("mov.b64 %0, {%1, %2};" : "=l"(r) : "f"(lo), "f"(hi));
    return r;
}
__device__ __forceinline__ void unpack2(unsigned long long v, float& lo, float& hi) {
    asm("mov.b64 {%0, %1}, %2;" : "=f"(lo), "=f"(hi) : "l"(v));
}
__device__ __forceinline__ unsigned long long fma2(unsigned long long a,
                                                   unsigned long long b,
                                                   unsigned long long c) {
    unsigned long long r;
    asm("fma.rn.f32x2 %0, %1, %2, %3;" : "=l"(r) : "l"(a), "l"(b), "l"(c));
    return r;
}
__device__ __forceinline__ unsigned long long add2(unsigned long long a,
                                                   unsigned long long b) {
    unsigned long long r;
    asm("add.rn.f32x2 %0, %1, %2;" : "=l"(r) : "l"(a), "l"(b));
    return r;
}
__device__ __forceinline__ unsigned long long mul2(unsigned long long a,
                                                   unsigned long long b) {
    unsigned long long r;
    asm("mul.rn.f32x2 %0, %1, %2;" : "=l"(r) : "l"(a), "l"(b));
    return r;
}

// ---------------- single kernel: adaptive 3x3 fast path + cold full-5x5 path ----------------
__global__ __launch_bounds__(GTX * GTY) void bilateral_pass(
    const float* __restrict__ in, float* __restrict__ out,
    const float* __restrict__ sigma_xyz, const float* __restrict__ sigma_r,
    int pass)
{
    const float LOG2E = 1.4426950408889634f;
    const float sx = sigma_xyz[2 * pass + 0];
    const float sy = sigma_xyz[2 * pass + 1];
    const float sr = sigma_r[pass];

    const float axn = 0.5f / (sx * sx);
    const float ayn = 0.5f / (sy * sy);
    const float axl = axn * LOG2E;               // log2-domain spatial coeffs
    const float ayl = ayn * LOG2E;
    const float ar  = (0.5f / (sr * sr)) * LOG2E;
    const float nar = -ar;
    const float axyl = axl + ayl;

    const int b   = blockIdx.z;
    const int gx0 = blockIdx.x * GBLKX + threadIdx.x * 4;   // first pixel col
    const int gy0 = blockIdx.y * GBLKY + threadIdx.y * 4;   // first pixel row
    const float* img = in  + (size_t)b * (H * W);
    float*       op  = out + (size_t)b * (H * W);

    // ---- adaptive truncation decision (uniform across launch) ----
    // error bound for dropping the 16 |d|=2 taps: per tap <= ws * sr * e^{-1/2}; den >= 1.
    {
        const float w1x = __expf(-axn), w4x = __expf(-4.f * axn);
        const float w1y = __expf(-ayn), w4y = __expf(-4.f * ayn);
        const float ring = 2.f * w4x * (1.f + 2.f * w1y + 2.f * w4y)
                         + 2.f * w4y * (1.f + 2.f * w1x);
        if (!(ring * 0.6065307f * sr < 1e-4f)) {
            // -------- cold path: exact full 5x5, direct gmem, minimal registers --------
            #pragma unroll 1
            for (int r = 0; r < 4; r++) {
                #pragma unroll 1
                for (int i = 0; i < 4; i++) {
                    const int py = gy0 + r, px = gx0 + i;
                    const float c = img[py * W + px];
                    float num = c, den = 1.0f;
                    #pragma unroll 1
                    for (int dy = -2; dy <= 2; dy++) {
                        const int yy = min(max(py + dy, 0), H - 1);
                        #pragma unroll 1
                        for (int dx = -2; dx <= 2; dx++) {
                            if ((dx | dy) == 0) continue;
                            const int xx = min(max(px + dx, 0), W - 1);
                            const float nb = img[yy * W + xx];
                            const float d  = nb - c;
                            const float s  = fmaf((float)(dx * dx), axl,
                                                  (float)(dy * dy) * ayl);
                            const float w  = ex2_approx(fmaf(d * d, nar, -s));
                            num = fmaf(w, nb, num);
                            den += w;
                        }
                    }
                    op[py * W + px] = __fdividef(num, den);
                }
            }
            return;
        }
    }

    // -------- fast path: 3x3, d-form packed f32x2 taps --------
    const unsigned long long nar2 = pack2(nar, nar);
    // pass-level packed (negated) spatial constants for the 4 tap pairs
    const unsigned long long ns_a = pack2(-axyl, -ayl);   // (t[i],   t[i+1])
    const unsigned long long ns_b = pack2(-axyl, -axl);   // (t[i+2], m[i])
    const unsigned long long ns_c = pack2(-axl, -axyl);   // (m[i+2], b[i])
    const unsigned long long ns_d = pack2(-ayl, -axyl);   // (b[i+1], b[i+2])

    // clamped edge columns (only ones that can go OOB)
    const int xm1 = max(gx0 - 1, 0);
    const int xp4 = min(gx0 + 4, W - 1);

    // 4-slot row ring, 6 floats per row (cols gx0-1 .. gx0+4)
    float rows[4][6];

    #define LOAD_ROW(SLOT, RY) {                                        \
        const int ryc = min(max((RY), 0), H - 1);                       \
        const float* rp = img + ryc * W;                                \
        const float4 m = *(const float4*)(rp + gx0);                    \
        rows[SLOT][0] = rp[xm1];                                        \
        rows[SLOT][1] = m.x; rows[SLOT][2] = m.y;                       \
        rows[SLOT][3] = m.z; rows[SLOT][4] = m.w;                       \
        rows[SLOT][5] = rp[xp4];                                        \
    }

    // prime: rows gy0-1, gy0, gy0+1
    LOAD_ROW(0, gy0 - 1)
    LOAD_ROW(1, gy0)
    LOAD_ROW(2, gy0 + 1)

    #pragma unroll
    for (int r = 0; r < 4; r++) {
        // prefetch next bottom row (one iteration ahead)
        if (r < 3) LOAD_ROW((r + 3) & 3, gy0 + 2 + r)

        const float* top = rows[(r    ) & 3];
        const float* mid = rows[(r + 1) & 3];
        const float* bot = rows[(r + 2) & 3];

        float4 res;
        float* resp = &res.x;
        #pragma unroll
        for (int i = 0; i < 4; i++) {
            const float c  = mid[i + 1];
            const unsigned long long nc2 = pack2(-c, -c);

            // packed accumulators; center tap (w==1) folded into init
            unsigned long long num2 = pack2(c, 0.f);
            unsigned long long den2 = pack2(1.f, 0.f);

            // d-form paired taps: d = nb - c; arg = nar*d^2 - s (all f32x2
            // except the two scalar EX2s); spatial consts are pass-level.
            #define TAPP(NB_A, NB_B, NS2) {                               \
                const unsigned long long nb2 = pack2((NB_A), (NB_B));     \
                const unsigned long long d2  = add2(nb2, nc2);            \
                const unsigned long long u2  = mul2(d2, nar2);            \
                const unsigned long long g2  = fma2(d2, u2, (NS2));       \
                float ga, gb;  unpack2(g2, ga, gb);                       \
                const unsigned long long w2 = pack2(ex2_approx(ga),       \
                                                    ex2_approx(gb));      \
                num2 = fma2(w2, nb2, num2);                               \
                den2 = add2(den2, w2);                                    \
            }

            TAPP(top[i],   top[i+1], ns_a)
            TAPP(top[i+2], mid[i],   ns_b)
            TAPP(mid[i+2], bot[i],   ns_c)
            TAPP(bot[i+1], bot[i+2], ns_d)
            #undef TAPP

            float na, nb_, da, db;
            unpack2(num2, na, nb_);
            unpack2(den2, da, db);
            resp[i] = __fdividef(na + nb_, da + db);
        }

        *(float4*)(op + (gy0 + r) * W + gx0) = res;
    }
    #undef LOAD_ROW
}

extern "C" void kernel_launch(void* const* d_in, const int* in_sizes, int n_in,
                              void* d_out, int out_size)
{
    const float* x         = (const float*)d_in[0];
    const float* sigma_xyz = (const float*)d_in[1];
    const float* sigma_r   = (const float*)d_in[2];
    float* out = (float*)d_out;

    const int B = in_sizes[0] / (H * W);

    float* buf0;
    float* buf1;
    cudaGetSymbolAddress((void**)&buf0, g_buf0);
    cudaGetSymbolAddress((void**)&buf1, g_buf1);

    dim3 fblock(GTX, GTY, 1);
    dim3 fgrid(W / GBLKX, H / GBLKY, B);

    bilateral_pass<<<fgrid, fblock>>>(x,    buf0, sigma_xyz, sigma_r, 0);
    bilateral_pass<<<fgrid, fblock>>>(buf0, buf1, sigma_xyz, sigma_r, 1);
    bilateral_pass<<<fgrid, fblock>>>(buf1, out,  sigma_xyz, sigma_r, 2);
}

// round 10
// speedup vs baseline: 2.1302x; 1.1102x over previous
#include <cuda_runtime.h>
#include <cstdint>

#define HW 2
#define H 512
#define W 512

// ---- geometry: 4-wide x 4-tall per thread, direct gmem ----
#define GTX 8                        // threads x (each covers 4 px)
#define GTY 16                       // threads y (each covers 4 rows)
#define GBLKX 32                     // px per block in x
#define GBLKY 64                     // px per block in y

typedef unsigned long long u64;

// scratch (allocation-free rule -> device globals)
__device__ float g_buf0[32 * H * W];
__device__ float g_buf1[32 * H * W];

__device__ __forceinline__ float ex2_approx(float x) {
    float y;
    asm("ex2.approx.ftz.f32 %0, %1;" : "=f"(y) : "f"(x));
    return y;
}

// packed f32x2 helpers (Blackwell FFMA2/FADD2/FMUL2 — only reachable via PTX)
__device__ __forceinline__ u64 pack2(float lo, float hi) {
    u64 r;
    asm("mov.b64 %0, {%1, %2};" : "=l"(r) : "f"(lo), "f"(hi));
    return r;
}
__device__ __forceinline__ void unpack2(u64 v, float& lo, float& hi) {
    asm("mov.b64 {%0, %1}, %2;" : "=f"(lo), "=f"(hi) : "l"(v));
}
__device__ __forceinline__ u64 fma2(u64 a, u64 b, u64 c) {
    u64 r;
    asm("fma.rn.f32x2 %0, %1, %2, %3;" : "=l"(r) : "l"(a), "l"(b), "l"(c));
    return r;
}
__device__ __forceinline__ u64 add2(u64 a, u64 b) {
    u64 r;
    asm("add.rn.f32x2 %0, %1, %2;" : "=l"(r) : "l"(a), "l"(b));
    return r;
}
__device__ __forceinline__ u64 mul2(u64 a, u64 b) {
    u64 r;
    asm("mul.rn.f32x2 %0, %1, %2;" : "=l"(r) : "l"(a), "l"(b));
    return r;
}

// ---------------- single kernel: adaptive 3x3 fast path + cold full-5x5 path ----------------
__global__ __launch_bounds__(GTX * GTY) void bilateral_pass(
    const float* __restrict__ in, float* __restrict__ out,
    const float* __restrict__ sigma_xyz, const float* __restrict__ sigma_r,
    int pass)
{
    const float LOG2E = 1.4426950408889634f;
    const float sx = sigma_xyz[2 * pass + 0];
    const float sy = sigma_xyz[2 * pass + 1];
    const float sr = sigma_r[pass];

    const float axn = 0.5f / (sx * sx);
    const float ayn = 0.5f / (sy * sy);
    const float axl = axn * LOG2E;               // log2-domain spatial coeffs
    const float ayl = ayn * LOG2E;
    const float ar  = (0.5f / (sr * sr)) * LOG2E;
    const float nar = -ar;
    const float axyl = axl + ayl;

    const int b   = blockIdx.z;
    const int gx0 = blockIdx.x * GBLKX + threadIdx.x * 4;   // first pixel col
    const int gy0 = blockIdx.y * GBLKY + threadIdx.y * 4;   // first pixel row
    const float* img = in  + (size_t)b * (H * W);
    float*       op  = out + (size_t)b * (H * W);

    // ---- adaptive truncation decision (uniform across launch) ----
    // error bound for dropping the 16 |d|=2 taps: per tap <= ws * sr * e^{-1/2}; den >= 1.
    {
        const float w1x = __expf(-axn), w4x = __expf(-4.f * axn);
        const float w1y = __expf(-ayn), w4y = __expf(-4.f * ayn);
        const float ring = 2.f * w4x * (1.f + 2.f * w1y + 2.f * w4y)
                         + 2.f * w4y * (1.f + 2.f * w1x);
        if (!(ring * 0.6065307f * sr < 1e-4f)) {
            // -------- cold path: exact full 5x5, direct gmem, minimal registers --------
            #pragma unroll 1
            for (int r = 0; r < 4; r++) {
                #pragma unroll 1
                for (int i = 0; i < 4; i++) {
                    const int py = gy0 + r, px = gx0 + i;
                    const float c = img[py * W + px];
                    float num = c, den = 1.0f;
                    #pragma unroll 1
                    for (int dy = -2; dy <= 2; dy++) {
                        const int yy = min(max(py + dy, 0), H - 1);
                        #pragma unroll 1
                        for (int dx = -2; dx <= 2; dx++) {
                            if ((dx | dy) == 0) continue;
                            const int xx = min(max(px + dx, 0), W - 1);
                            const float nb = img[yy * W + xx];
                            const float d  = nb - c;
                            const float s  = fmaf((float)(dx * dx), axl,
                                                  (float)(dy * dy) * ayl);
                            const float w  = ex2_approx(fmaf(d * d, nar, -s));
                            num = fmaf(w, nb, num);
                            den += w;
                        }
                    }
                    op[py * W + px] = __fdividef(num, den);
                }
            }
            return;
        }
    }

    // -------- fast path: 3x3, packed taps + symmetric-edge weight cache --------
    const u64 nar2    = pack2(nar, nar);
    const u64 negone2 = pack2(-1.0f, -1.0f);
    const u64 one2    = pack2(1.0f, 1.0f);
    const u64 ns_xy2  = pack2(-axyl, -axyl);   // |dx|=1,|dy|=1
    const u64 ns_y2   = pack2(-ayl,  -ayl);    // dx=0,|dy|=1
    const u64 ns_x2   = pack2(-axl,  -axl);    // |dx|=1,dy=0

    // clamped edge columns (only ones that can go OOB)
    const int xm1 = max(gx0 - 1, 0);
    const int xp4 = min(gx0 + 4, W - 1);

    // 4-slot row ring, 6 floats per row (cols gx0-1 .. gx0+4)
    float rows[4][6];

    #define LOAD_ROW(SLOT, RY) {                                        \
        const int ryc = min(max((RY), 0), H - 1);                       \
        const float* rp = img + ryc * W;                                \
        const float4 m = *(const float4*)(rp + gx0);                    \
        rows[SLOT][0] = rp[xm1];                                        \
        rows[SLOT][1] = m.x; rows[SLOT][2] = m.y;                       \
        rows[SLOT][3] = m.z; rows[SLOT][4] = m.w;                       \
        rows[SLOT][5] = rp[xp4];                                        \
    }

    // prime: rows gy0-1, gy0, gy0+1
    LOAD_ROW(0, gy0 - 1)
    LOAD_ROW(1, gy0)
    LOAD_ROW(2, gy0 + 1)

    // compute edge weight pair: d = nb - c; w = ex2(nar*d^2 + ns)
    #define EDGE2(W2, NB2, NS2, C2) {                    \
        const u64 d2 = fma2((C2), negone2, (NB2));       \
        const u64 u2 = mul2(d2, nar2);                   \
        const u64 g2 = fma2(d2, u2, (NS2));              \
        float ga, gb;  unpack2(g2, ga, gb);              \
        (W2) = pack2(ex2_approx(ga), ex2_approx(gb));    \
    }
    #define APPLY(W2, NB2, NUM2, DEN2) {                 \
        (NUM2) = fma2((W2), (NB2), (NUM2));              \
        (DEN2) = add2((DEN2), (W2));                     \
    }

    // bot-edge weight cache: w(u, dxc) for u=0..3, dxc=-1,0,+1
    u64 wm1A, w0A, wp1A, wm1B, w0B, wp1B;

    #pragma unroll
    for (int r = 0; r < 4; r++) {
        // prefetch next bottom row (one iteration ahead)
        if (r < 3) LOAD_ROW((r + 3) & 3, gy0 + 2 + r)

        const float* top = rows[(r    ) & 3];
        const float* mid = rows[(r + 1) & 3];
        const float* bot = rows[(r + 2) & 3];

        // pair A = px cols 0,1 (mid[1],mid[2]); pair B = px cols 2,3 (mid[3],mid[4])
        const u64 c2A = pack2(mid[1], mid[2]);
        const u64 c2B = pack2(mid[3], mid[4]);

        // center taps (w == 1 exactly) folded into init
        u64 numA = c2A, denA = one2;
        u64 numB = c2B, denB = one2;

        // packed top-row neighbor values
        const u64 t_m1A = pack2(top[0], top[1]);
        const u64 t_0A  = pack2(top[1], top[2]);
        const u64 t_p1A = pack2(top[2], top[3]);
        const u64 t_m1B = t_p1A;                   // (top[2], top[3])
        const u64 t_0B  = pack2(top[3], top[4]);
        const u64 t_p1B = pack2(top[4], top[5]);

        if (r == 0) {
            // first row: all top edges fresh
            u64 w;
            EDGE2(w, t_m1A, ns_xy2, c2A) APPLY(w, t_m1A, numA, denA)
            EDGE2(w, t_0A,  ns_y2,  c2A) APPLY(w, t_0A,  numA, denA)
            EDGE2(w, t_p1A, ns_xy2, c2A) APPLY(w, t_p1A, numA, denA)
            EDGE2(w, t_m1B, ns_xy2, c2B) APPLY(w, t_m1B, numB, denB)
            EDGE2(w, t_0B,  ns_y2,  c2B) APPLY(w, t_0B,  numB, denB)
            EDGE2(w, t_p1B, ns_xy2, c2B) APPLY(w, t_p1B, numB, denB)
        } else {
            // cached top edges (= previous iteration's bot edges, symmetric)
            APPLY(w0A, t_0A, numA, denA)
            APPLY(w0B, t_0B, numB, denB)

            // two boundary edges not in cache: (u=-1,dxc=+1) and (u=4,dxc=-1)
            const float df1 = top[0] - mid[1];
            const float wf1 = ex2_approx(fmaf(df1, df1 * nar, -axyl));
            const float df2 = top[5] - mid[4];
            const float wf2 = ex2_approx(fmaf(df2, df2 * nar, -axyl));

            float m1Alo, m1Ahi, m1Blo, m1Bhi, p1Alo, p1Ahi, p1Blo, p1Bhi;
            unpack2(wm1A, m1Alo, m1Ahi);
            unpack2(wm1B, m1Blo, m1Bhi);
            unpack2(wp1A, p1Alo, p1Ahi);
            unpack2(wp1B, p1Blo, p1Bhi);

            // top dx=-1 taps: weights = cached (u=v-1, dxc=+1)
            { const u64 w2 = pack2(wf1,   p1Alo); APPLY(w2, t_m1A, numA, denA) }
            { const u64 w2 = pack2(p1Ahi, p1Blo); APPLY(w2, t_m1B, numB, denB) }
            // top dx=+1 taps: weights = cached (u=v+1, dxc=-1)
            { const u64 w2 = pack2(m1Ahi, m1Blo); APPLY(w2, t_p1A, numA, denA) }
            { const u64 w2 = pack2(m1Bhi, wf2);   APPLY(w2, t_p1B, numB, denB) }
        }

        // mid-row taps (fresh)
        {
            u64 w;
            const u64 nbAl = pack2(mid[0], mid[1]);
            const u64 nbAr = pack2(mid[2], mid[3]);
            const u64 nbBl = nbAr;
            const u64 nbBr = pack2(mid[4], mid[5]);
            EDGE2(w, nbAl, ns_x2, c2A) APPLY(w, nbAl, numA, denA)
            EDGE2(w, nbAr, ns_x2, c2A) APPLY(w, nbAr, numA, denA)
            EDGE2(w, nbBl, ns_x2, c2B) APPLY(w, nbBl, numB, denB)
            EDGE2(w, nbBr, ns_x2, c2B) APPLY(w, nbBr, numB, denB)
        }

        // bot-row taps (fresh; cache weights for next iteration's top)
        {
            const u64 b_m1A = pack2(bot[0], bot[1]);
            const u64 b_0A  = pack2(bot[1], bot[2]);
            const u64 b_p1A = pack2(bot[2], bot[3]);
            const u64 b_m1B = b_p1A;
            const u64 b_0B  = pack2(bot[3], bot[4]);
            const u64 b_p1B = pack2(bot[4], bot[5]);
            EDGE2(wm1A, b_m1A, ns_xy2, c2A) APPLY(wm1A, b_m1A, numA, denA)
            EDGE2(w0A,  b_0A,  ns_y2,  c2A) APPLY(w0A,  b_0A,  numA, denA)
            EDGE2(wp1A, b_p1A, ns_xy2, c2A) APPLY(wp1A, b_p1A, numA, denA)
            EDGE2(wm1B, b_m1B, ns_xy2, c2B) APPLY(wm1B, b_m1B, numB, denB)
            EDGE2(w0B,  b_0B,  ns_y2,  c2B) APPLY(w0B,  b_0B,  numB, denB)
            EDGE2(wp1B, b_p1B, ns_xy2, c2B) APPLY(wp1B, b_p1B, numB, denB)
        }

        float n0, n1, n2, n3, d0, d1, d2, d3;
        unpack2(numA, n0, n1); unpack2(denA, d0, d1);
        unpack2(numB, n2, n3); unpack2(denB, d2, d3);
        float4 res;
        res.x = __fdividef(n0, d0);
        res.y = __fdividef(n1, d1);
        res.z = __fdividef(n2, d2);
        res.w = __fdividef(n3, d3);
        *(float4*)(op + (gy0 + r) * W + gx0) = res;
    }
    #undef LOAD_ROW
    #undef EDGE2
    #undef APPLY
}

extern "C" void kernel_launch(void* const* d_in, const int* in_sizes, int n_in,
                              void* d_out, int out_size)
{
    const float* x         = (const float*)d_in[0];
    const float* sigma_xyz = (const float*)d_in[1];
    const float* sigma_r   = (const float*)d_in[2];
    float* out = (float*)d_out;

    const int B = in_sizes[0] / (H * W);

    float* buf0;
    float* buf1;
    cudaGetSymbolAddress((void**)&buf0, g_buf0);
    cudaGetSymbolAddress((void**)&buf1, g_buf1);

    dim3 fblock(GTX, GTY, 1);
    dim3 fgrid(W / GBLKX, H / GBLKY, B);

    bilateral_pass<<<fgrid, fblock>>>(x,    buf0, sigma_xyz, sigma_r, 0);
    bilateral_pass<<<fgrid, fblock>>>(buf0, buf1, sigma_xyz, sigma_r, 1);
    bilateral_pass<<<fgrid, fblock>>>(buf1, out,  sigma_xyz, sigma_r, 2);
}